// round 9
// baseline (speedup 1.0000x reference)
#include <cuda_runtime.h>
#include <cuda_fp16.h>
#include <cstdint>

// Deformable Conv2d: B=8, C=3, H=W=512, O=16, K=3, PAD=1.
// R9: contraction via base-ISA tensor cores (mma.sync.m16n8k16.f32.f16.f16.f32):
//  - x repacked -> zero-padded NHWC fp16x4 (unconditional LDG.64 gathers)
//  - per warp: 32 pixels; each thread samples 27 taps, packs f16, STS.128 to
//    an 80B-strided smem tile (conflict-free for STS.128 and ldmatrix)
//  - 4x ldmatrix.x4 + 8x mma.sync per warp; bias preloaded into C accumulators
//  - B fragments (16x27 weights, zero-padded to 32x16) built once per thread

#define Bn 8
#define Cc 3
#define Hh 512
#define Ww 512
#define Oo 16
#define KK 9
#define HW (Hh * Ww)

#define PROWS 515
#define PSTRIDE 516
#define PTOT (PROWS * PSTRIDE)

#define WITER 8
#define NWARPGROUPS (Bn * HW / 32)                   // 65536
#define NCTAS (NWARPGROUPS / (4 * WITER))            // 2048

#define A_ROW_BYTES 80                               // 32 f16 data + pad
#define A_WARP_BYTES (32 * A_ROW_BYTES)              // 2560

__device__ uint2 g_xh[Bn * PTOT];                    // padded fp16x4 image

__device__ __forceinline__ uint32_t smem_u32(const void* p) {
    uint32_t a;
    asm("{ .reg .u64 t; cvta.to.shared.u64 t, %1; cvt.u32.u64 %0, t; }"
        : "=r"(a) : "l"(p));
    return a;
}
__device__ __forceinline__ uint32_t pack_f16x2(float lo, float hi) {
    uint32_t r;
    asm("cvt.rn.f16x2.f32 %0, %1, %2;" : "=r"(r) : "f"(hi), "f"(lo));
    return r;
}

// ---------------- repack ----------------
__global__ __launch_bounds__(256) void repack_kernel(const float* __restrict__ x)
{
    int i = blockIdx.x * 256 + threadIdx.x;
    if (i >= Bn * PTOT) return;
    int b = i / PTOT;
    int p = i % PTOT;
    int yy = p / PSTRIDE;
    int xx = p % PSTRIDE;

    uint2 u = make_uint2(0u, 0u);
    if (yy >= 1 && yy <= Hh && xx >= 1 && xx <= Ww) {
        const float* xb = x + (size_t)b * Cc * HW + (size_t)(yy - 1) * Ww + (xx - 1);
        __half2 h01 = __floats2half2_rn(xb[0], xb[HW]);
        __half2 h23 = __floats2half2_rn(xb[2 * HW], 0.0f);
        u.x = *reinterpret_cast<unsigned int*>(&h01);
        u.y = *reinterpret_cast<unsigned int*>(&h23);
    }
    g_xh[i] = u;
}

// sample 3 channels at (py, px)
__device__ __forceinline__ void sample3(
    const uint2* __restrict__ xtb, float py, float px,
    float& s0, float& s1, float& s2)
{
    py = fminf(fmaxf(py, -1.0f), 512.0f);
    px = fminf(fmaxf(px, -1.0f), 512.0f);

    float y0f = floorf(py);
    float x0f = floorf(px);
    float fy = py - y0f;
    float fx = px - x0f;
    int y0 = (int)y0f;
    int x0 = (int)x0f;

    int base = (y0 + 1) * PSTRIDE + (x0 + 1);

    uint2 u00 = __ldg(xtb + base);
    uint2 u01 = __ldg(xtb + base + 1);
    uint2 u10 = __ldg(xtb + base + PSTRIDE);
    uint2 u11 = __ldg(xtb + base + PSTRIDE + 1);

    float w00 = (1.0f - fy) * (1.0f - fx);
    float w01 = (1.0f - fy) * fx;
    float w10 = fy * (1.0f - fx);
    float w11 = fy * fx;

    float2 a00 = __half22float2(*reinterpret_cast<__half2*>(&u00.x));
    float2 c00 = __half22float2(*reinterpret_cast<__half2*>(&u00.y));
    float2 a01 = __half22float2(*reinterpret_cast<__half2*>(&u01.x));
    float2 c01 = __half22float2(*reinterpret_cast<__half2*>(&u01.y));
    float2 a10 = __half22float2(*reinterpret_cast<__half2*>(&u10.x));
    float2 c10 = __half22float2(*reinterpret_cast<__half2*>(&u10.y));
    float2 a11 = __half22float2(*reinterpret_cast<__half2*>(&u11.x));
    float2 c11 = __half22float2(*reinterpret_cast<__half2*>(&u11.y));

    s0 = fmaf(w00, a00.x, fmaf(w01, a01.x, fmaf(w10, a10.x, w11 * a11.x)));
    s1 = fmaf(w00, a00.y, fmaf(w01, a01.y, fmaf(w10, a10.y, w11 * a11.y)));
    s2 = fmaf(w00, c00.x, fmaf(w01, c01.x, fmaf(w10, c10.x, w11 * c11.x)));
}

// B[k][n] of the (32x16) zero-padded weight matrix: k = tap*3 + c
__device__ __forceinline__ float bval(const float* __restrict__ weight, int k, int n)
{
    if (k >= 27) return 0.0f;
    int tap = k / 3;
    int c = k % 3;
    return __ldg(weight + n * 27 + c * KK + tap);
}

// ---------------- main kernel ----------------
__global__ __launch_bounds__(128) void dcn_kernel(
    const float* __restrict__ off,
    const float* __restrict__ weight,
    const float* __restrict__ bias,
    float* __restrict__ out)
{
    __shared__ __align__(16) char sA[4 * A_WARP_BYTES];

    int tid = threadIdx.x;
    int wid = tid >> 5;
    int lane = tid & 31;
    int g = lane >> 2;       // groupID
    int tig = lane & 3;      // thread-in-group

    const uint32_t sAwarp = smem_u32(sA) + wid * A_WARP_BYTES;
    const uint32_t stsAddr = sAwarp + lane * A_ROW_BYTES;
    const uint32_t lmBase = sAwarp + (lane & 15) * A_ROW_BYTES + (lane >> 4) * 16;

    // --- B fragments: [kc][nt] -> 2 regs each ---
    uint32_t bf[2][2][2];
#pragma unroll
    for (int kc = 0; kc < 2; kc++)
#pragma unroll
        for (int nt = 0; nt < 2; nt++) {
            int n = nt * 8 + g;
            int k0 = kc * 16 + tig * 2;
            bf[kc][nt][0] = pack_f16x2(bval(weight, k0,     n), bval(weight, k0 + 1, n));
            bf[kc][nt][1] = pack_f16x2(bval(weight, k0 + 8, n), bval(weight, k0 + 9, n));
        }

    // --- bias for the D columns this thread owns ---
    float bia[2][2];   // [nt][0/1] -> o = nt*8 + tig*2 (+1)
#pragma unroll
    for (int nt = 0; nt < 2; nt++) {
        bia[nt][0] = __ldg(bias + nt * 8 + tig * 2);
        bia[nt][1] = __ldg(bias + nt * 8 + tig * 2 + 1);
    }

#pragma unroll 1
    for (int it = 0; it < WITER; it++) {
        int gw = (blockIdx.x * 4 + wid) * WITER + it;    // warp-group id
        int pbase = gw * 32;
        int wcb = pbase & (Ww - 1);
        int h = (pbase >> 9) & (Hh - 1);
        int b = pbase >> 18;
        int wc = wcb + lane;

        const uint2* xtb = g_xh + (size_t)b * PTOT;
        const float* ob = off + (size_t)b * (2 * KK) * HW + (size_t)h * Ww + wc;

        // ---- sample 27 taps ----
        float sv[27];
#pragma unroll
        for (int k = 0; k < KK; k++) {
            const int ky = k / 3;
            const int kx = k % 3;
            float dy = __ldg(ob + (size_t)(2 * k) * HW);
            float dx = __ldg(ob + (size_t)(2 * k + 1) * HW);
            sample3(xtb, dy + (float)(ky - 1 + h), dx + (float)(kx - 1 + wc),
                    sv[3 * k + 0], sv[3 * k + 1], sv[3 * k + 2]);
        }

        // ---- pack to f16 and stage row 'lane' ----
        uint32_t q[14];
#pragma unroll
        for (int j = 0; j < 13; j++) q[j] = pack_f16x2(sv[2 * j], sv[2 * j + 1]);
        q[13] = pack_f16x2(sv[26], 0.0f);

        asm volatile("st.shared.v4.b32 [%0], {%1,%2,%3,%4};"
                     :: "r"(stsAddr), "r"(q[0]), "r"(q[1]), "r"(q[2]), "r"(q[3]) : "memory");
        asm volatile("st.shared.v4.b32 [%0], {%1,%2,%3,%4};"
                     :: "r"(stsAddr + 16), "r"(q[4]), "r"(q[5]), "r"(q[6]), "r"(q[7]) : "memory");
        asm volatile("st.shared.v4.b32 [%0], {%1,%2,%3,%4};"
                     :: "r"(stsAddr + 32), "r"(q[8]), "r"(q[9]), "r"(q[10]), "r"(q[11]) : "memory");
        asm volatile("st.shared.v4.b32 [%0], {%1,%2,%3,%4};"
                     :: "r"(stsAddr + 48), "r"(q[12]), "r"(q[13]), "r"(0u), "r"(0u) : "memory");
        __syncwarp();

        // ---- D accumulators init with bias ----
        float d[2][2][4];
#pragma unroll
        for (int mt = 0; mt < 2; mt++)
#pragma unroll
            for (int nt = 0; nt < 2; nt++) {
                d[mt][nt][0] = bia[nt][0];
                d[mt][nt][1] = bia[nt][1];
                d[mt][nt][2] = bia[nt][0];
                d[mt][nt][3] = bia[nt][1];
            }

        // ---- ldmatrix + mma ----
#pragma unroll
        for (int mt = 0; mt < 2; mt++) {
#pragma unroll
            for (int kc = 0; kc < 2; kc++) {
                uint32_t a0, a1, a2, a3;
                uint32_t addr = lmBase + mt * (16 * A_ROW_BYTES) + kc * 32;
                asm volatile("ldmatrix.sync.aligned.m8n8.x4.shared.b16 {%0,%1,%2,%3}, [%4];"
                             : "=r"(a0), "=r"(a1), "=r"(a2), "=r"(a3) : "r"(addr));
#pragma unroll
                for (int nt = 0; nt < 2; nt++) {
                    asm volatile(
                        "mma.sync.aligned.m16n8k16.row.col.f32.f16.f16.f32 "
                        "{%0,%1,%2,%3}, {%4,%5,%6,%7}, {%8,%9}, {%0,%1,%2,%3};"
                        : "+f"(d[mt][nt][0]), "+f"(d[mt][nt][1]),
                          "+f"(d[mt][nt][2]), "+f"(d[mt][nt][3])
                        : "r"(a0), "r"(a1), "r"(a2), "r"(a3),
                          "r"(bf[kc][nt][0]), "r"(bf[kc][nt][1]));
                }
            }
        }
        __syncwarp();   // WAR: protect staging buffer before next iteration

        // ---- store: D[row=pixel][col=o] ----
        float* op = out + (size_t)b * Oo * HW + (size_t)h * Ww + wcb;
#pragma unroll
        for (int mt = 0; mt < 2; mt++) {
            int px = mt * 16 + g;
#pragma unroll
            for (int nt = 0; nt < 2; nt++) {
                int o0 = nt * 8 + tig * 2;
                op[(size_t)o0 * HW + px]           = d[mt][nt][0];
                op[(size_t)(o0 + 1) * HW + px]     = d[mt][nt][1];
                op[(size_t)o0 * HW + px + 8]       = d[mt][nt][2];
                op[(size_t)(o0 + 1) * HW + px + 8] = d[mt][nt][3];
            }
        }
    }
}

extern "C" void kernel_launch(void* const* d_in, const int* in_sizes, int n_in,
                              void* d_out, int out_size)
{
    const float* x      = (const float*)d_in[0];
    const float* off    = (const float*)d_in[1];
    const float* weight = (const float*)d_in[2];
    const float* bias   = (const float*)d_in[3];
    float* out          = (float*)d_out;

    int ptotal = Bn * PTOT;
    repack_kernel<<<(ptotal + 255) / 256, 256>>>(x);

    dcn_kernel<<<NCTAS, 128>>>(off, weight, bias, out);
}

// round 10
// speedup vs baseline: 1.1902x; 1.1902x over previous
#include <cuda_runtime.h>
#include <cuda_fp16.h>
#include <cstdint>

// Deformable Conv2d: B=8, C=3, H=W=512, O=16, K=3, PAD=1.
// R10 = R9 (mma.sync contraction) + software pipelining:
//  - double-buffered per-warp A staging; sample/pack of group t+1 overlaps
//    ldmatrix/mma/stores of group t
//  - WITER=4, 4096 CTAs of 128 threads

#define Bn 8
#define Cc 3
#define Hh 512
#define Ww 512
#define Oo 16
#define KK 9
#define HW (Hh * Ww)

#define PROWS 515
#define PSTRIDE 516
#define PTOT (PROWS * PSTRIDE)

#define WITER 4
#define NGROUPS (Bn * HW / 32)                       // 65536
#define NCTAS (NGROUPS / (4 * WITER))                // 4096

#define A_ROW_BYTES 80                               // 32 f16 + 16B pad
#define A_WARP_BYTES (32 * A_ROW_BYTES)              // 2560

__device__ uint2 g_xh[Bn * PTOT];                    // padded fp16x4 image

__device__ __forceinline__ uint32_t smem_u32(const void* p) {
    uint32_t a;
    asm("{ .reg .u64 t; cvta.to.shared.u64 t, %1; cvt.u32.u64 %0, t; }"
        : "=r"(a) : "l"(p));
    return a;
}
__device__ __forceinline__ uint32_t pack_f16x2(float lo, float hi) {
    uint32_t r;
    asm("cvt.rn.f16x2.f32 %0, %1, %2;" : "=r"(r) : "f"(hi), "f"(lo));
    return r;
}

// ---------------- repack ----------------
__global__ __launch_bounds__(256) void repack_kernel(const float* __restrict__ x)
{
    int i = blockIdx.x * 256 + threadIdx.x;
    if (i >= Bn * PTOT) return;
    int b = i / PTOT;
    int p = i % PTOT;
    int yy = p / PSTRIDE;
    int xx = p % PSTRIDE;

    uint2 u = make_uint2(0u, 0u);
    if (yy >= 1 && yy <= Hh && xx >= 1 && xx <= Ww) {
        const float* xb = x + (size_t)b * Cc * HW + (size_t)(yy - 1) * Ww + (xx - 1);
        __half2 h01 = __floats2half2_rn(xb[0], xb[HW]);
        __half2 h23 = __floats2half2_rn(xb[2 * HW], 0.0f);
        u.x = *reinterpret_cast<unsigned int*>(&h01);
        u.y = *reinterpret_cast<unsigned int*>(&h23);
    }
    g_xh[i] = u;
}

__device__ __forceinline__ void sample3(
    const uint2* __restrict__ xtb, float py, float px,
    float& s0, float& s1, float& s2)
{
    py = fminf(fmaxf(py, -1.0f), 512.0f);
    px = fminf(fmaxf(px, -1.0f), 512.0f);

    float y0f = floorf(py);
    float x0f = floorf(px);
    float fy = py - y0f;
    float fx = px - x0f;
    int y0 = (int)y0f;
    int x0 = (int)x0f;

    int base = (y0 + 1) * PSTRIDE + (x0 + 1);

    uint2 u00 = __ldg(xtb + base);
    uint2 u01 = __ldg(xtb + base + 1);
    uint2 u10 = __ldg(xtb + base + PSTRIDE);
    uint2 u11 = __ldg(xtb + base + PSTRIDE + 1);

    float w00 = (1.0f - fy) * (1.0f - fx);
    float w01 = (1.0f - fy) * fx;
    float w10 = fy * (1.0f - fx);
    float w11 = fy * fx;

    float2 a00 = __half22float2(*reinterpret_cast<__half2*>(&u00.x));
    float2 c00 = __half22float2(*reinterpret_cast<__half2*>(&u00.y));
    float2 a01 = __half22float2(*reinterpret_cast<__half2*>(&u01.x));
    float2 c01 = __half22float2(*reinterpret_cast<__half2*>(&u01.y));
    float2 a10 = __half22float2(*reinterpret_cast<__half2*>(&u10.x));
    float2 c10 = __half22float2(*reinterpret_cast<__half2*>(&u10.y));
    float2 a11 = __half22float2(*reinterpret_cast<__half2*>(&u11.x));
    float2 c11 = __half22float2(*reinterpret_cast<__half2*>(&u11.y));

    s0 = fmaf(w00, a00.x, fmaf(w01, a01.x, fmaf(w10, a10.x, w11 * a11.x)));
    s1 = fmaf(w00, a00.y, fmaf(w01, a01.y, fmaf(w10, a10.y, w11 * a11.y)));
    s2 = fmaf(w00, c00.x, fmaf(w01, c01.x, fmaf(w10, c10.x, w11 * c11.x)));
}

// sample all 27 taps of the pixel in group gw owned by 'lane', pack to f16x2
__device__ __forceinline__ void sample_pack(
    const float* __restrict__ off, int gw, int lane, uint32_t q[14])
{
    int pbase = gw * 32;
    int wcb = pbase & (Ww - 1);
    int h = (pbase >> 9) & (Hh - 1);
    int b = pbase >> 18;
    int wc = wcb + lane;

    const uint2* xtb = g_xh + (size_t)b * PTOT;
    const float* ob = off + (size_t)b * (2 * KK) * HW + (size_t)h * Ww + wc;

    float sv[27];
#pragma unroll
    for (int k = 0; k < KK; k++) {
        const int ky = k / 3;
        const int kx = k % 3;
        float dy = __ldg(ob + (size_t)(2 * k) * HW);
        float dx = __ldg(ob + (size_t)(2 * k + 1) * HW);
        sample3(xtb, dy + (float)(ky - 1 + h), dx + (float)(kx - 1 + wc),
                sv[3 * k + 0], sv[3 * k + 1], sv[3 * k + 2]);
    }
#pragma unroll
    for (int j = 0; j < 13; j++) q[j] = pack_f16x2(sv[2 * j], sv[2 * j + 1]);
    q[13] = pack_f16x2(sv[26], 0.0f);
}

// B[k][n] of the (32x16) zero-padded weight matrix: k = tap*3 + c
__device__ __forceinline__ float bval(const float* __restrict__ weight, int k, int n)
{
    if (k >= 27) return 0.0f;
    int tap = k / 3;
    int c = k % 3;
    return __ldg(weight + n * 27 + c * KK + tap);
}

// ---------------- main kernel ----------------
__global__ __launch_bounds__(128, 6) void dcn_kernel(
    const float* __restrict__ off,
    const float* __restrict__ weight,
    const float* __restrict__ bias,
    float* __restrict__ out)
{
    __shared__ __align__(16) char sA[4 * 2 * A_WARP_BYTES];   // [warp][buf]

    int tid = threadIdx.x;
    int wid = tid >> 5;
    int lane = tid & 31;
    int g = lane >> 2;
    int tig = lane & 3;

    const uint32_t sAwarp = smem_u32(sA) + wid * (2 * A_WARP_BYTES);

    // --- B fragments ---
    uint32_t bf[2][2][2];
#pragma unroll
    for (int kc = 0; kc < 2; kc++)
#pragma unroll
        for (int nt = 0; nt < 2; nt++) {
            int n = nt * 8 + g;
            int k0 = kc * 16 + tig * 2;
            bf[kc][nt][0] = pack_f16x2(bval(weight, k0,     n), bval(weight, k0 + 1, n));
            bf[kc][nt][1] = pack_f16x2(bval(weight, k0 + 8, n), bval(weight, k0 + 9, n));
        }

    float bia[2][2];
#pragma unroll
    for (int nt = 0; nt < 2; nt++) {
        bia[nt][0] = __ldg(bias + nt * 8 + tig * 2);
        bia[nt][1] = __ldg(bias + nt * 8 + tig * 2 + 1);
    }

    const int gw0 = (blockIdx.x * 4 + wid) * WITER;

    uint32_t q[14];
    sample_pack(off, gw0, lane, q);

#pragma unroll
    for (int t = 0; t < WITER; t++) {
        const uint32_t bufBase = sAwarp + (uint32_t)(t & 1) * A_WARP_BYTES;
        const uint32_t stsAddr = bufBase + lane * A_ROW_BYTES;
        const uint32_t lmBase  = bufBase + (lane & 15) * A_ROW_BYTES + (lane >> 4) * 16;

        asm volatile("st.shared.v4.b32 [%0], {%1,%2,%3,%4};"
                     :: "r"(stsAddr), "r"(q[0]), "r"(q[1]), "r"(q[2]), "r"(q[3]) : "memory");
        asm volatile("st.shared.v4.b32 [%0], {%1,%2,%3,%4};"
                     :: "r"(stsAddr + 16), "r"(q[4]), "r"(q[5]), "r"(q[6]), "r"(q[7]) : "memory");
        asm volatile("st.shared.v4.b32 [%0], {%1,%2,%3,%4};"
                     :: "r"(stsAddr + 32), "r"(q[8]), "r"(q[9]), "r"(q[10]), "r"(q[11]) : "memory");
        asm volatile("st.shared.v4.b32 [%0], {%1,%2,%3,%4};"
                     :: "r"(stsAddr + 48), "r"(q[12]), "r"(q[13]), "r"(0u), "r"(0u) : "memory");
        __syncwarp();

        // ---- prefetch next group's samples (overlaps the mma below) ----
        if (t + 1 < WITER)
            sample_pack(off, gw0 + t + 1, lane, q);

        // ---- mma for group gw0 + t ----
        float d[2][2][4];
#pragma unroll
        for (int mt = 0; mt < 2; mt++)
#pragma unroll
            for (int nt = 0; nt < 2; nt++) {
                d[mt][nt][0] = bia[nt][0];
                d[mt][nt][1] = bia[nt][1];
                d[mt][nt][2] = bia[nt][0];
                d[mt][nt][3] = bia[nt][1];
            }

#pragma unroll
        for (int mt = 0; mt < 2; mt++) {
#pragma unroll
            for (int kc = 0; kc < 2; kc++) {
                uint32_t a0, a1, a2, a3;
                uint32_t addr = lmBase + mt * (16 * A_ROW_BYTES) + kc * 32;
                asm volatile("ldmatrix.sync.aligned.m8n8.x4.shared.b16 {%0,%1,%2,%3}, [%4];"
                             : "=r"(a0), "=r"(a1), "=r"(a2), "=r"(a3) : "r"(addr));
#pragma unroll
                for (int nt = 0; nt < 2; nt++) {
                    asm volatile(
                        "mma.sync.aligned.m16n8k16.row.col.f32.f16.f16.f32 "
                        "{%0,%1,%2,%3}, {%4,%5,%6,%7}, {%8,%9}, {%0,%1,%2,%3};"
                        : "+f"(d[mt][nt][0]), "+f"(d[mt][nt][1]),
                          "+f"(d[mt][nt][2]), "+f"(d[mt][nt][3])
                        : "r"(a0), "r"(a1), "r"(a2), "r"(a3),
                          "r"(bf[kc][nt][0]), "r"(bf[kc][nt][1]));
                }
            }
        }

        // ---- store group gw0 + t ----
        {
            int pbase = (gw0 + t) * 32;
            int wcb = pbase & (Ww - 1);
            int h = (pbase >> 9) & (Hh - 1);
            int b = pbase >> 18;
            float* op = out + (size_t)b * Oo * HW + (size_t)h * Ww + wcb;
#pragma unroll
            for (int mt = 0; mt < 2; mt++) {
                int px = mt * 16 + g;
#pragma unroll
                for (int nt = 0; nt < 2; nt++) {
                    int o0 = nt * 8 + tig * 2;
                    op[(size_t)o0 * HW + px]           = d[mt][nt][0];
                    op[(size_t)(o0 + 1) * HW + px]     = d[mt][nt][1];
                    op[(size_t)o0 * HW + px + 8]       = d[mt][nt][2];
                    op[(size_t)(o0 + 1) * HW + px + 8] = d[mt][nt][3];
                }
            }
        }
    }
}

extern "C" void kernel_launch(void* const* d_in, const int* in_sizes, int n_in,
                              void* d_out, int out_size)
{
    const float* x      = (const float*)d_in[0];
    const float* off    = (const float*)d_in[1];
    const float* weight = (const float*)d_in[2];
    const float* bias   = (const float*)d_in[3];
    float* out          = (float*)d_out;

    int ptotal = Bn * PTOT;
    repack_kernel<<<(ptotal + 255) / 256, 256>>>(x);

    dcn_kernel<<<NCTAS, 128>>>(off, weight, bias, out);
}

// round 11
// speedup vs baseline: 1.5127x; 1.2709x over previous
#include <cuda_runtime.h>
#include <cuda_fp16.h>
#include <cstdint>

// Deformable Conv2d: B=8, C=3, H=W=512, O=16, K=3, PAD=1.
// R11 = R6 architecture (scalar gathers + f32x2 const contraction) with:
//  - prep_weights folded into repack kernel (one launch fewer)
//  - single combined constant upload (weights+bias)
//  - x-lerp of the bilinear blend done in fp16 half2 (HSUB2/HFMA2), y-lerp fp32

#define Bn 8
#define Cc 3
#define Hh 512
#define Ww 512
#define Oo 16
#define KK 9
#define HW (Hh * Ww)

#define PROWS 515            // padded coords: 0..514
#define PSTRIDE 516
#define PTOT (PROWS * PSTRIDE)

#define NW (KK * Cc * 8)     // 216 packed weight pairs
#define NC (NW + 8)          // + 8 packed bias pairs = 224

__device__ uint2 g_xh[Bn * PTOT];            // padded fp16x4 image
__device__ unsigned long long g_stage[NC];   // staging: weights then bias

__constant__ unsigned long long cst[NC];

__device__ __forceinline__ unsigned long long pack_pair(float a, float b)
{
    unsigned long long u;
    asm("mov.b64 %0, {%1, %2};" : "=l"(u) : "f"(a), "f"(b));
    return u;
}
__device__ __forceinline__ unsigned long long pack2(float v)
{
    unsigned long long u;
    asm("mov.b64 %0, {%1, %1};" : "=l"(u) : "f"(v));
    return u;
}
__device__ __forceinline__ __half2 asH2(uint32_t u)
{
    return *reinterpret_cast<__half2*>(&u);
}

// ---------------- repack + weight prep ----------------
__global__ __launch_bounds__(256) void repack_kernel(
    const float* __restrict__ x,
    const float* __restrict__ weight,
    const float* __restrict__ bias)
{
    // block 0 also packs weights/bias into the staging buffer
    if (blockIdx.x == 0) {
        int i = threadIdx.x;
        if (i < NW) {
            int k = i / (Cc * 8);
            int r = i % (Cc * 8);
            int c = r / 8;
            int j = r % 8;
            float w0 = weight[(2 * j + 0) * (Cc * KK) + c * KK + k];
            float w1 = weight[(2 * j + 1) * (Cc * KK) + c * KK + k];
            g_stage[i] = pack_pair(w0, w1);
        } else if (i < NC) {
            int j = i - NW;
            g_stage[i] = pack_pair(bias[2 * j], bias[2 * j + 1]);
        }
    }

    int i = blockIdx.x * 256 + threadIdx.x;
    if (i >= Bn * PTOT) return;
    int b = i / PTOT;
    int p = i % PTOT;
    int yy = p / PSTRIDE;
    int xx = p % PSTRIDE;

    uint2 u = make_uint2(0u, 0u);
    if (yy >= 1 && yy <= Hh && xx >= 1 && xx <= Ww) {
        const float* xb = x + (size_t)b * Cc * HW + (size_t)(yy - 1) * Ww + (xx - 1);
        __half2 h01 = __floats2half2_rn(xb[0], xb[HW]);
        __half2 h23 = __floats2half2_rn(xb[2 * HW], 0.0f);
        u.x = *reinterpret_cast<unsigned int*>(&h01);
        u.y = *reinterpret_cast<unsigned int*>(&h23);
    }
    g_xh[i] = u;
}

// ---------------- main kernel ----------------
__global__ __launch_bounds__(256, 4) void dcn_kernel(
    const float* __restrict__ off,
    float* __restrict__ out)
{
    int idx = blockIdx.x * 256 + threadIdx.x;    // exact grid
    int w = idx & (Ww - 1);
    int h = (idx >> 9) & (Hh - 1);
    int b = idx >> 18;

    const uint2* xtb = g_xh + (size_t)b * PTOT;
    const float* ob = off + (size_t)b * (2 * KK) * HW + (size_t)h * Ww + w;

    const float hf = (float)h;
    const float wf = (float)w;

    unsigned long long accp[8];
#pragma unroll
    for (int j = 0; j < 8; j++) accp[j] = cst[NW + j];

#pragma unroll
    for (int k = 0; k < KK; k++) {
        const int ky = k / 3;
        const int kx = k % 3;
        float dy = __ldg(ob + (size_t)(2 * k) * HW);
        float dx = __ldg(ob + (size_t)(2 * k + 1) * HW);

        float py = dy + (hf + (float)(ky - 1));
        float px = dx + (wf + (float)(kx - 1));

        // clamp to [-1, 512]: identical result (border zeros / weight 0)
        py = fminf(fmaxf(py, -1.0f), 512.0f);
        px = fminf(fmaxf(px, -1.0f), 512.0f);

        float y0f = floorf(py);
        float x0f = floorf(px);
        float fy = py - y0f;
        float fx = px - x0f;
        int y0 = (int)y0f;
        int x0 = (int)x0f;

        int base = (y0 + 1) * PSTRIDE + (x0 + 1);

        uint2 u00 = __ldg(xtb + base);
        uint2 u01 = __ldg(xtb + base + 1);
        uint2 u10 = __ldg(xtb + base + PSTRIDE);
        uint2 u11 = __ldg(xtb + base + PSTRIDE + 1);

        // ---- x-lerp in fp16 (half2), y-lerp in fp32 ----
        __half2 fx2 = __float2half2_rn(fx);
        __half2 t01 = __hfma2(fx2, __hsub2(asH2(u01.x), asH2(u00.x)), asH2(u00.x));
        __half2 b01 = __hfma2(fx2, __hsub2(asH2(u11.x), asH2(u10.x)), asH2(u10.x));
        __half2 t2  = __hfma2(fx2, __hsub2(asH2(u01.y), asH2(u00.y)), asH2(u00.y));
        __half2 b2  = __hfma2(fx2, __hsub2(asH2(u11.y), asH2(u10.y)), asH2(u10.y));

        float2 tf01 = __half22float2(t01);
        float2 bf01 = __half22float2(b01);
        float  tf2  = __low2float(t2);
        float  bf2  = __low2float(b2);

        float s0 = fmaf(fy, bf01.x - tf01.x, tf01.x);
        float s1 = fmaf(fy, bf01.y - tf01.y, tf01.y);
        float s2 = fmaf(fy, bf2 - tf2, tf2);

        unsigned long long sp0 = pack2(s0);
        unsigned long long sp1 = pack2(s1);
        unsigned long long sp2 = pack2(s2);

#pragma unroll
        for (int j = 0; j < 8; j++) {
            asm("fma.rn.f32x2 %0, %1, %2, %0;"
                : "+l"(accp[j]) : "l"(sp0), "l"(cst[(k * Cc + 0) * 8 + j]));
            asm("fma.rn.f32x2 %0, %1, %2, %0;"
                : "+l"(accp[j]) : "l"(sp1), "l"(cst[(k * Cc + 1) * 8 + j]));
            asm("fma.rn.f32x2 %0, %1, %2, %0;"
                : "+l"(accp[j]) : "l"(sp2), "l"(cst[(k * Cc + 2) * 8 + j]));
        }
    }

    float* ot = out + (size_t)b * Oo * HW + (size_t)h * Ww + w;
#pragma unroll
    for (int j = 0; j < 8; j++) {
        float lo, hi;
        asm("mov.b64 {%0, %1}, %2;" : "=f"(lo), "=f"(hi) : "l"(accp[j]));
        ot[(size_t)(2 * j + 0) * HW] = lo;
        ot[(size_t)(2 * j + 1) * HW] = hi;
    }
}

extern "C" void kernel_launch(void* const* d_in, const int* in_sizes, int n_in,
                              void* d_out, int out_size)
{
    const float* x      = (const float*)d_in[0];
    const float* off    = (const float*)d_in[1];
    const float* weight = (const float*)d_in[2];
    const float* bias   = (const float*)d_in[3];
    float* out          = (float*)d_out;

    int ptotal = Bn * PTOT;
    repack_kernel<<<(ptotal + 255) / 256, 256>>>(x, weight, bias);

    void* src = nullptr;
    cudaGetSymbolAddress(&src, g_stage);
    cudaMemcpyToSymbolAsync(cst, src, NC * sizeof(unsigned long long),
                            0, cudaMemcpyDeviceToDevice);

    int total = Bn * HW;                 // 2,097,152
    dcn_kernel<<<total / 256, 256>>>(off, out);
}

// round 13
// speedup vs baseline: 1.6086x; 1.0634x over previous
#include <cuda_runtime.h>
#include <cuda_fp16.h>
#include <cstdint>

// Deformable Conv2d: B=8, C=3, H=W=512, O=16, K=3, PAD=1.
// R13 = R12 with the illegal scalar st.global.L2::evict_first replaced by
// st.global.cs (streaming store, any width). Loads keep evict_first.
//  - vertical-pair image layout: g[(y,x)] = 16B {ch(y,x), ch(y+1,x)} so each
//    bilinear tap needs only 2 LDG.128 (left pair, right pair)
//  - streaming hints on offsets (read-once) and output (write-once) so the
//    gather image stays resident in L2

#define Bn 8
#define Cc 3
#define Hh 512
#define Ww 512
#define Oo 16
#define KK 9
#define HW (Hh * Ww)

#define PROWS 514            // row index yy = y0+1, y0 in [-1,512]
#define PSTRIDE 516
#define PTOT (PROWS * PSTRIDE)

#define NW (KK * Cc * 8)     // 216 packed weight pairs
#define NC (NW + 8)          // + 8 packed bias pairs

__device__ uint4 g_xp[Bn * PTOT];            // vertical-pair fp16 image (~34MB)
__device__ unsigned long long g_stage[NC];

__constant__ unsigned long long cst[NC];

__device__ __forceinline__ unsigned long long pack_pair(float a, float b)
{
    unsigned long long u;
    asm("mov.b64 %0, {%1, %2};" : "=l"(u) : "f"(a), "f"(b));
    return u;
}
__device__ __forceinline__ unsigned long long pack2(float v)
{
    unsigned long long u;
    asm("mov.b64 %0, {%1, %1};" : "=l"(u) : "f"(v));
    return u;
}
__device__ __forceinline__ __half2 asH2(uint32_t u)
{
    return *reinterpret_cast<__half2*>(&u);
}
__device__ __forceinline__ float ldg_stream(const float* p)
{
    float v;
    asm volatile("ld.global.nc.cs.f32 %0, [%1];" : "=f"(v) : "l"(p));
    return v;
}
__device__ __forceinline__ void stg_stream(float* p, float v)
{
    asm volatile("st.global.cs.f32 [%0], %1;" :: "l"(p), "f"(v) : "memory");
}

// ---------------- repack + weight prep ----------------
__global__ __launch_bounds__(256) void repack_kernel(
    const float* __restrict__ x,
    const float* __restrict__ weight,
    const float* __restrict__ bias)
{
    if (blockIdx.x == 0) {
        int i = threadIdx.x;
        if (i < NW) {
            int k = i / (Cc * 8);
            int r = i % (Cc * 8);
            int c = r / 8;
            int j = r % 8;
            float w0 = weight[(2 * j + 0) * (Cc * KK) + c * KK + k];
            float w1 = weight[(2 * j + 1) * (Cc * KK) + c * KK + k];
            g_stage[i] = pack_pair(w0, w1);
        } else if (i < NC) {
            int j = i - NW;
            g_stage[i] = pack_pair(bias[2 * j], bias[2 * j + 1]);
        }
    }

    int i = blockIdx.x * 256 + threadIdx.x;
    if (i >= Bn * PTOT) return;
    int b = i / PTOT;
    int p = i % PTOT;
    int yy = p / PSTRIDE;
    int xx = p % PSTRIDE;

    // top row = yy-1, bottom row = yy (image coords), col = xx-1
    uint4 u = make_uint4(0u, 0u, 0u, 0u);
    bool cx = (xx >= 1) && (xx <= Ww);
    if (cx) {
        const float* xb = x + (size_t)b * Cc * HW + (xx - 1);
        if (yy >= 1 && yy <= Hh) {                 // top valid
            const float* pt = xb + (size_t)(yy - 1) * Ww;
            __half2 h01 = __floats2half2_rn(pt[0], pt[HW]);
            __half2 h23 = __floats2half2_rn(pt[2 * HW], 0.0f);
            u.x = *reinterpret_cast<unsigned int*>(&h01);
            u.y = *reinterpret_cast<unsigned int*>(&h23);
        }
        if (yy < Hh) {                              // bottom valid (row yy)
            const float* pb = xb + (size_t)yy * Ww;
            __half2 h01 = __floats2half2_rn(pb[0], pb[HW]);
            __half2 h23 = __floats2half2_rn(pb[2 * HW], 0.0f);
            u.z = *reinterpret_cast<unsigned int*>(&h01);
            u.w = *reinterpret_cast<unsigned int*>(&h23);
        }
    }
    g_xp[i] = u;
}

// ---------------- main kernel ----------------
__global__ __launch_bounds__(256, 4) void dcn_kernel(
    const float* __restrict__ off,
    float* __restrict__ out)
{
    int idx = blockIdx.x * 256 + threadIdx.x;    // exact grid
    int w = idx & (Ww - 1);
    int h = (idx >> 9) & (Hh - 1);
    int b = idx >> 18;

    const uint4* xtb = g_xp + (size_t)b * PTOT;
    const float* ob = off + (size_t)b * (2 * KK) * HW + (size_t)h * Ww + w;

    const float hf = (float)h;
    const float wf = (float)w;

    unsigned long long accp[8];
#pragma unroll
    for (int j = 0; j < 8; j++) accp[j] = cst[NW + j];

#pragma unroll
    for (int k = 0; k < KK; k++) {
        const int ky = k / 3;
        const int kx = k % 3;
        float dy = ldg_stream(ob + (size_t)(2 * k) * HW);
        float dx = ldg_stream(ob + (size_t)(2 * k + 1) * HW);

        float py = dy + (hf + (float)(ky - 1));
        float px = dx + (wf + (float)(kx - 1));

        py = fminf(fmaxf(py, -1.0f), 512.0f);
        px = fminf(fmaxf(px, -1.0f), 512.0f);

        float y0f = floorf(py);
        float x0f = floorf(px);
        float fy = py - y0f;
        float fx = px - x0f;
        int y0 = (int)y0f;
        int x0 = (int)x0f;

        int base = (y0 + 1) * PSTRIDE + (x0 + 1);

        uint4 uL = __ldg(xtb + base);       // {top(c0c1), top(c2-), bot(c0c1), bot(c2-)} at x0
        uint4 uR = __ldg(xtb + base + 1);   // same at x0+1

        // ---- x-lerp in fp16, y-lerp in fp32 ----
        __half2 fx2 = __float2half2_rn(fx);
        __half2 t01 = __hfma2(fx2, __hsub2(asH2(uR.x), asH2(uL.x)), asH2(uL.x));
        __half2 t2  = __hfma2(fx2, __hsub2(asH2(uR.y), asH2(uL.y)), asH2(uL.y));
        __half2 b01 = __hfma2(fx2, __hsub2(asH2(uR.z), asH2(uL.z)), asH2(uL.z));
        __half2 b2  = __hfma2(fx2, __hsub2(asH2(uR.w), asH2(uL.w)), asH2(uL.w));

        float2 tf01 = __half22float2(t01);
        float2 bf01 = __half22float2(b01);
        float  tf2  = __low2float(t2);
        float  bf2  = __low2float(b2);

        float s0 = fmaf(fy, bf01.x - tf01.x, tf01.x);
        float s1 = fmaf(fy, bf01.y - tf01.y, tf01.y);
        float s2 = fmaf(fy, bf2 - tf2, tf2);

        unsigned long long sp0 = pack2(s0);
        unsigned long long sp1 = pack2(s1);
        unsigned long long sp2 = pack2(s2);

#pragma unroll
        for (int j = 0; j < 8; j++) {
            asm("fma.rn.f32x2 %0, %1, %2, %0;"
                : "+l"(accp[j]) : "l"(sp0), "l"(cst[(k * Cc + 0) * 8 + j]));
            asm("fma.rn.f32x2 %0, %1, %2, %0;"
                : "+l"(accp[j]) : "l"(sp1), "l"(cst[(k * Cc + 1) * 8 + j]));
            asm("fma.rn.f32x2 %0, %1, %2, %0;"
                : "+l"(accp[j]) : "l"(sp2), "l"(cst[(k * Cc + 2) * 8 + j]));
        }
    }

    float* ot = out + (size_t)b * Oo * HW + (size_t)h * Ww + w;
#pragma unroll
    for (int j = 0; j < 8; j++) {
        float lo, hi;
        asm("mov.b64 {%0, %1}, %2;" : "=f"(lo), "=f"(hi) : "l"(accp[j]));
        stg_stream(ot + (size_t)(2 * j + 0) * HW, lo);
        stg_stream(ot + (size_t)(2 * j + 1) * HW, hi);
    }
}

extern "C" void kernel_launch(void* const* d_in, const int* in_sizes, int n_in,
                              void* d_out, int out_size)
{
    const float* x      = (const float*)d_in[0];
    const float* off    = (const float*)d_in[1];
    const float* weight = (const float*)d_in[2];
    const float* bias   = (const float*)d_in[3];
    float* out          = (float*)d_out;

    int ptotal = Bn * PTOT;
    repack_kernel<<<(ptotal + 255) / 256, 256>>>(x, weight, bias);

    void* src = nullptr;
    cudaGetSymbolAddress(&src, g_stage);
    cudaMemcpyToSymbolAsync(cst, src, NC * sizeof(unsigned long long),
                            0, cudaMemcpyDeviceToDevice);

    int total = Bn * HW;                 // 2,097,152
    dcn_kernel<<<total / 256, 256>>>(off, out);
}